// round 4
// baseline (speedup 1.0000x reference)
#include <cuda_runtime.h>

#define NNODES 100000
#define NEDGES 3200000
#define FIN 512
#define FOUT 256
#define TOTE (NEDGES + NNODES)

// ---------------- scratch (device globals; zero-init bss) ----------------
__device__ __align__(16) float g_h0[(size_t)NNODES * FOUT];  // normalized feats
__device__ __align__(16) float g_za[(size_t)NNODES * FOUT];  // ping buffer
__device__ int   g_cnt[NNODES];
__device__ float g_dinv[NNODES];
__device__ int   g_rowptr[NNODES + 1];
__device__ int   g_fill[NNODES];
__device__ int   g_bsum[512];
__device__ int   g_srcs[TOTE];
__device__ float g_nrm[TOTE];
__device__ int   g_is64;

// ---------------- edge dtype detection ----------------
// int64 node ids < 1e5 have zero high words; int32 ids at odd slots are
// random nonzero values. Sample 65536 odd words.
__global__ void k_detect(const int* __restrict__ e32, int E) {
    __shared__ int nz;
    if (threadIdx.x == 0) nz = 0;
    __syncthreads();
    int lim = min(E, 65536);
    for (int i = threadIdx.x; i < lim; i += blockDim.x)
        if (e32[2 * i + 1] != 0) nz = 1;   // benign race
    __syncthreads();
    if (threadIdx.x == 0) g_is64 = (nz == 0) ? 1 : 0;
}

__device__ __forceinline__ int edge_at(const void* ei, long long idx) {
    if (g_is64) return (int)((const long long*)ei)[idx];
    return ((const int*)ei)[idx];
}

// ---------------- graph preprocessing ----------------
__global__ void k_zero(int n) {
    int i = blockIdx.x * blockDim.x + threadIdx.x;
    if (i < n) { g_cnt[i] = 0; g_fill[i] = 0; }
}

__global__ void k_count(const void* __restrict__ ei, int E, int n) {
    int i = blockIdx.x * blockDim.x + threadIdx.x;
    if (i < E) {
        int d = edge_at(ei, (long long)E + i);
        d = min(max(d, 0), n - 1);          // defensive clamp
        atomicAdd(&g_cnt[d], 1);
    }
}

__global__ void k_dinv(int n) {
    int i = blockIdx.x * blockDim.x + threadIdx.x;
    if (i < n) {
        int c = g_cnt[i] + 1;               // + self loop
        g_cnt[i] = c;
        g_dinv[i] = rsqrtf((float)c);
    }
}

// Exclusive scan of g_cnt -> g_rowptr. 256-thread blocks.
__global__ void k_scanA(int n) {
    __shared__ int sh[256];
    int tid = threadIdx.x;
    int i = blockIdx.x * 256 + tid;
    int v = (i < n) ? g_cnt[i] : 0;
    sh[tid] = v;
    __syncthreads();
    for (int off = 1; off < 256; off <<= 1) {
        int t = (tid >= off) ? sh[tid - off] : 0;
        __syncthreads();
        sh[tid] += t;
        __syncthreads();
    }
    if (i < n) g_rowptr[i] = sh[tid] - v;   // exclusive
    if (tid == 255) g_bsum[blockIdx.x] = sh[255];
}

__global__ void k_scanB(int nb) {   // single block, 512 threads, nb <= 512
    __shared__ int sh[512];
    int tid = threadIdx.x;
    int v = (tid < nb) ? g_bsum[tid] : 0;
    sh[tid] = v;
    __syncthreads();
    for (int off = 1; off < 512; off <<= 1) {
        int t = (tid >= off) ? sh[tid - off] : 0;
        __syncthreads();
        sh[tid] += t;
        __syncthreads();
    }
    g_bsum[tid] = sh[tid] - v;              // exclusive
}

__global__ void k_scanC(int n, int total) {
    int i = blockIdx.x * blockDim.x + threadIdx.x;
    if (i < n) g_rowptr[i] += g_bsum[i >> 8];
    if (i == 0) g_rowptr[n] = total;
}

__global__ void k_scatter(const void* __restrict__ ei, int E, int n) {
    int i = blockIdx.x * blockDim.x + threadIdx.x;
    int tot = E + n;
    if (i >= tot) return;
    int s, d;
    if (i < E) {
        s = edge_at(ei, i);
        d = edge_at(ei, (long long)E + i);
        s = min(max(s, 0), n - 1);          // defensive clamp
        d = min(max(d, 0), n - 1);
    } else {
        s = d = i - E;
    }
    int pos = g_rowptr[d] + atomicAdd(&g_fill[d], 1);
    pos = min(max(pos, 0), tot - 1);        // defensive clamp
    g_srcs[pos] = s;
    g_nrm[pos]  = g_dinv[s] * g_dinv[d];
}

// ---------------- fused GEMM + bias + L2-normalize*1.8 -> g_h0 ----------------
// 64-row x 256-col block tile, BK=16, 256 threads, 8x8 per-thread micro-tile.
__global__ __launch_bounds__(256) void k_gemm(const float* __restrict__ x,
                                              const float* __restrict__ W,
                                              const float* __restrict__ b,
                                              int N) {
    __shared__ __align__(16) float As[16][64];
    __shared__ __align__(16) float Ws[16][256];
    int tid = threadIdx.x;
    int tx = tid & 31, ty = tid >> 5;
    int n0 = blockIdx.x * 64;

    float acc[8][8];
#pragma unroll
    for (int i = 0; i < 8; i++)
#pragma unroll
        for (int j = 0; j < 8; j++) acc[i][j] = 0.0f;

    for (int k0 = 0; k0 < FIN; k0 += 16) {
        {
            int r = tid >> 2, kq = (tid & 3) * 4;
            float4 v = make_float4(0.f, 0.f, 0.f, 0.f);
            int row = n0 + r;
            if (row < N) v = *(const float4*)&x[(size_t)row * FIN + k0 + kq];
            As[kq + 0][r] = v.x; As[kq + 1][r] = v.y;
            As[kq + 2][r] = v.z; As[kq + 3][r] = v.w;
        }
        {
            int o = tid;
            const float* wp = &W[(size_t)o * FIN + k0];
            float4 w0 = *(const float4*)(wp);
            float4 w1 = *(const float4*)(wp + 4);
            float4 w2 = *(const float4*)(wp + 8);
            float4 w3 = *(const float4*)(wp + 12);
            Ws[0][o] = w0.x;  Ws[1][o] = w0.y;  Ws[2][o] = w0.z;  Ws[3][o] = w0.w;
            Ws[4][o] = w1.x;  Ws[5][o] = w1.y;  Ws[6][o] = w1.z;  Ws[7][o] = w1.w;
            Ws[8][o] = w2.x;  Ws[9][o] = w2.y;  Ws[10][o] = w2.z; Ws[11][o] = w2.w;
            Ws[12][o] = w3.x; Ws[13][o] = w3.y; Ws[14][o] = w3.z; Ws[15][o] = w3.w;
        }
        __syncthreads();
#pragma unroll
        for (int kk = 0; kk < 16; kk++) {
            float4 a0 = *(const float4*)&As[kk][ty * 8];
            float4 a1 = *(const float4*)&As[kk][ty * 8 + 4];
            float4 b0 = *(const float4*)&Ws[kk][tx * 8];
            float4 b1 = *(const float4*)&Ws[kk][tx * 8 + 4];
            float a[8]  = {a0.x, a0.y, a0.z, a0.w, a1.x, a1.y, a1.z, a1.w};
            float bb[8] = {b0.x, b0.y, b0.z, b0.w, b1.x, b1.y, b1.z, b1.w};
#pragma unroll
            for (int i = 0; i < 8; i++)
#pragma unroll
                for (int j = 0; j < 8; j++) acc[i][j] += a[i] * bb[j];
        }
        __syncthreads();
    }

    float bb[8];
#pragma unroll
    for (int j = 0; j < 8; j++) bb[j] = b[tx * 8 + j];
#pragma unroll
    for (int i = 0; i < 8; i++) {
        float ssq = 0.0f;
#pragma unroll
        for (int j = 0; j < 8; j++) {
            acc[i][j] += bb[j];
            ssq += acc[i][j] * acc[i][j];
        }
#pragma unroll
        for (int off = 16; off; off >>= 1)
            ssq += __shfl_xor_sync(0xffffffffu, ssq, off);
        float scale = 1.8f / fmaxf(sqrtf(ssq), 1e-12f);
        int row = n0 + ty * 8 + i;
        if (row < N) {
            float4 o0 = make_float4(acc[i][0] * scale, acc[i][1] * scale,
                                    acc[i][2] * scale, acc[i][3] * scale);
            float4 o1 = make_float4(acc[i][4] * scale, acc[i][5] * scale,
                                    acc[i][6] * scale, acc[i][7] * scale);
            *(float4*)&g_h0[(size_t)row * FOUT + tx * 8]     = o0;
            *(float4*)&g_h0[(size_t)row * FOUT + tx * 8 + 4] = o1;
        }
    }
}

// ---------------- APPNP step: one block per dst node, CSR gather ----------------
// insel: 0 = g_h0, 1 = g_za, 2 = dout;  outsel: 1 = g_za, 2 = dout
__global__ __launch_bounds__(256) void k_prop(int insel, int outsel,
                                              float* __restrict__ dout) {
    const float* zin;
    if (insel == 0)      zin = g_h0;
    else if (insel == 1) zin = g_za;
    else                 zin = dout;
    float* zout = (outsel == 1) ? g_za : dout;

    int node = blockIdx.x;
    int c = threadIdx.x;
    int beg = g_rowptr[node];
    int end = g_rowptr[node + 1];
    float acc = 0.0f;
    int e = beg;
    for (; e + 4 <= end; e += 4) {
        int s0 = g_srcs[e],     s1 = g_srcs[e + 1];
        int s2 = g_srcs[e + 2], s3 = g_srcs[e + 3];
        float w0 = g_nrm[e],     w1 = g_nrm[e + 1];
        float w2 = g_nrm[e + 2], w3 = g_nrm[e + 3];
        acc += w0 * zin[(size_t)s0 * FOUT + c];
        acc += w1 * zin[(size_t)s1 * FOUT + c];
        acc += w2 * zin[(size_t)s2 * FOUT + c];
        acc += w3 * zin[(size_t)s3 * FOUT + c];
    }
    for (; e < end; e++)
        acc += g_nrm[e] * zin[(size_t)g_srcs[e] * FOUT + c];
    float h = g_h0[(size_t)node * FOUT + c];
    zout[(size_t)node * FOUT + c] = 0.85f * acc + 0.15f * h;
}

// ---------------- launch ----------------
extern "C" void kernel_launch(void* const* d_in, const int* in_sizes, int n_in,
                              void* d_out, int out_size) {
    // Identify inputs by element count (order-independent):
    //   x: 51,200,000   edge_index: 6,400,000   W1: 131,072   b1: 256
    const float* x  = 0;
    const void*  ei = 0;
    const float* W1 = 0;
    const float* b1 = 0;
    for (int i = 0; i < n_in; i++) {
        int sz = in_sizes[i];
        if      (sz == NNODES * FIN) x  = (const float*)d_in[i];
        else if (sz == 2 * NEDGES)   ei = d_in[i];
        else if (sz == FOUT * FIN)   W1 = (const float*)d_in[i];
        else if (sz == FOUT)         b1 = (const float*)d_in[i];
    }
    float* out = (float*)d_out;
    int N = NNODES;
    int E = NEDGES;

    k_detect<<<1, 256>>>((const int*)ei, E);
    k_zero<<<(N + 255) / 256, 256>>>(N);
    k_count<<<(E + 255) / 256, 256>>>(ei, E, N);
    k_dinv<<<(N + 255) / 256, 256>>>(N);
    int nb = (N + 255) / 256;                 // 391 blocks
    k_scanA<<<nb, 256>>>(N);
    k_scanB<<<1, 512>>>(nb);
    k_scanC<<<(N + 255) / 256, 256>>>(N, E + N);
    k_scatter<<<(E + N + 255) / 256, 256>>>(ei, E, N);

    k_gemm<<<(N + 63) / 64, 256>>>(x, W1, b1, N);

    // APPNP: k even writes g_za, k odd writes d_out; k=9 lands in d_out.
    for (int k = 0; k < 10; k++) {
        int insel  = (k == 0) ? 0 : ((k & 1) ? 1 : 2);
        int outsel = (k & 1) ? 2 : 1;
        k_prop<<<N, 256>>>(insel, outsel, out);
    }
}

// round 5
// speedup vs baseline: 1.8481x; 1.8481x over previous
#include <cuda_runtime.h>

#define NNODES 100000
#define NEDGES 3200000
#define FIN 512
#define FOUT 256
#define TOTE (NEDGES + NNODES)

// ---------------- scratch (device globals; zero-init bss) ----------------
__device__ __align__(16) float g_h0[(size_t)NNODES * FOUT];  // normalized feats
__device__ __align__(16) float g_za[(size_t)NNODES * FOUT];  // ping buffer
__device__ int   g_cnt[NNODES];
__device__ float g_dinv[NNODES];
__device__ int   g_rowptr[NNODES + 1];
__device__ int   g_fill[NNODES];
__device__ int   g_bsum[512];
__device__ __align__(16) int2 g_edge[TOTE];   // (src, norm-as-int) packed
__device__ int   g_is64;

// ---------------- edge dtype detection ----------------
__global__ void k_detect(const int* __restrict__ e32, int E) {
    __shared__ int nz;
    if (threadIdx.x == 0) nz = 0;
    __syncthreads();
    int lim = min(E, 65536);
    for (int i = threadIdx.x; i < lim; i += blockDim.x)
        if (e32[2 * i + 1] != 0) nz = 1;   // benign race
    __syncthreads();
    if (threadIdx.x == 0) g_is64 = (nz == 0) ? 1 : 0;
}

__device__ __forceinline__ int edge_at(const void* ei, long long idx) {
    if (g_is64) return (int)((const long long*)ei)[idx];
    return ((const int*)ei)[idx];
}

// ---------------- graph preprocessing ----------------
__global__ void k_zero(int n) {
    int i = blockIdx.x * blockDim.x + threadIdx.x;
    if (i < n) { g_cnt[i] = 0; g_fill[i] = 0; }
}

__global__ void k_count(const void* __restrict__ ei, int E, int n) {
    int i = blockIdx.x * blockDim.x + threadIdx.x;
    if (i < E) {
        int d = edge_at(ei, (long long)E + i);
        d = min(max(d, 0), n - 1);
        atomicAdd(&g_cnt[d], 1);
    }
}

__global__ void k_dinv(int n) {
    int i = blockIdx.x * blockDim.x + threadIdx.x;
    if (i < n) {
        int c = g_cnt[i] + 1;               // + self loop
        g_cnt[i] = c;
        g_dinv[i] = rsqrtf((float)c);
    }
}

// Exclusive scan of g_cnt -> g_rowptr.
__global__ void k_scanA(int n) {
    __shared__ int sh[256];
    int tid = threadIdx.x;
    int i = blockIdx.x * 256 + tid;
    int v = (i < n) ? g_cnt[i] : 0;
    sh[tid] = v;
    __syncthreads();
    for (int off = 1; off < 256; off <<= 1) {
        int t = (tid >= off) ? sh[tid - off] : 0;
        __syncthreads();
        sh[tid] += t;
        __syncthreads();
    }
    if (i < n) g_rowptr[i] = sh[tid] - v;
    if (tid == 255) g_bsum[blockIdx.x] = sh[255];
}

__global__ void k_scanB(int nb) {
    __shared__ int sh[512];
    int tid = threadIdx.x;
    int v = (tid < nb) ? g_bsum[tid] : 0;
    sh[tid] = v;
    __syncthreads();
    for (int off = 1; off < 512; off <<= 1) {
        int t = (tid >= off) ? sh[tid - off] : 0;
        __syncthreads();
        sh[tid] += t;
        __syncthreads();
    }
    g_bsum[tid] = sh[tid] - v;
}

__global__ void k_scanC(int n, int total) {
    int i = blockIdx.x * blockDim.x + threadIdx.x;
    if (i < n) g_rowptr[i] += g_bsum[i >> 8];
    if (i == 0) g_rowptr[n] = total;
}

__global__ void k_scatter(const void* __restrict__ ei, int E, int n) {
    int i = blockIdx.x * blockDim.x + threadIdx.x;
    int tot = E + n;
    if (i >= tot) return;
    int s, d;
    if (i < E) {
        s = edge_at(ei, i);
        d = edge_at(ei, (long long)E + i);
        s = min(max(s, 0), n - 1);
        d = min(max(d, 0), n - 1);
    } else {
        s = d = i - E;
    }
    int pos = g_rowptr[d] + atomicAdd(&g_fill[d], 1);
    pos = min(max(pos, 0), tot - 1);
    float w = g_dinv[s] * g_dinv[d];
    g_edge[pos] = make_int2(s, __float_as_int(w));
}

// ---------------- fused GEMM + bias + L2-normalize*1.8 -> g_h0 ----------------
__global__ __launch_bounds__(256) void k_gemm(const float* __restrict__ x,
                                              const float* __restrict__ W,
                                              const float* __restrict__ b,
                                              int N) {
    __shared__ __align__(16) float As[16][64];
    __shared__ __align__(16) float Ws[16][256];
    int tid = threadIdx.x;
    int tx = tid & 31, ty = tid >> 5;
    int n0 = blockIdx.x * 64;

    float acc[8][8];
#pragma unroll
    for (int i = 0; i < 8; i++)
#pragma unroll
        for (int j = 0; j < 8; j++) acc[i][j] = 0.0f;

    for (int k0 = 0; k0 < FIN; k0 += 16) {
        {
            int r = tid >> 2, kq = (tid & 3) * 4;
            float4 v = make_float4(0.f, 0.f, 0.f, 0.f);
            int row = n0 + r;
            if (row < N) v = *(const float4*)&x[(size_t)row * FIN + k0 + kq];
            As[kq + 0][r] = v.x; As[kq + 1][r] = v.y;
            As[kq + 2][r] = v.z; As[kq + 3][r] = v.w;
        }
        {
            int o = tid;
            const float* wp = &W[(size_t)o * FIN + k0];
            float4 w0 = *(const float4*)(wp);
            float4 w1 = *(const float4*)(wp + 4);
            float4 w2 = *(const float4*)(wp + 8);
            float4 w3 = *(const float4*)(wp + 12);
            Ws[0][o] = w0.x;  Ws[1][o] = w0.y;  Ws[2][o] = w0.z;  Ws[3][o] = w0.w;
            Ws[4][o] = w1.x;  Ws[5][o] = w1.y;  Ws[6][o] = w1.z;  Ws[7][o] = w1.w;
            Ws[8][o] = w2.x;  Ws[9][o] = w2.y;  Ws[10][o] = w2.z; Ws[11][o] = w2.w;
            Ws[12][o] = w3.x; Ws[13][o] = w3.y; Ws[14][o] = w3.z; Ws[15][o] = w3.w;
        }
        __syncthreads();
#pragma unroll
        for (int kk = 0; kk < 16; kk++) {
            float4 a0 = *(const float4*)&As[kk][ty * 8];
            float4 a1 = *(const float4*)&As[kk][ty * 8 + 4];
            float4 b0 = *(const float4*)&Ws[kk][tx * 8];
            float4 b1 = *(const float4*)&Ws[kk][tx * 8 + 4];
            float a[8]  = {a0.x, a0.y, a0.z, a0.w, a1.x, a1.y, a1.z, a1.w};
            float bb[8] = {b0.x, b0.y, b0.z, b0.w, b1.x, b1.y, b1.z, b1.w};
#pragma unroll
            for (int i = 0; i < 8; i++)
#pragma unroll
                for (int j = 0; j < 8; j++) acc[i][j] += a[i] * bb[j];
        }
        __syncthreads();
    }

    float bb[8];
#pragma unroll
    for (int j = 0; j < 8; j++) bb[j] = b[tx * 8 + j];
#pragma unroll
    for (int i = 0; i < 8; i++) {
        float ssq = 0.0f;
#pragma unroll
        for (int j = 0; j < 8; j++) {
            acc[i][j] += bb[j];
            ssq += acc[i][j] * acc[i][j];
        }
#pragma unroll
        for (int off = 16; off; off >>= 1)
            ssq += __shfl_xor_sync(0xffffffffu, ssq, off);
        float scale = 1.8f / fmaxf(sqrtf(ssq), 1e-12f);
        int row = n0 + ty * 8 + i;
        if (row < N) {
            float4 o0 = make_float4(acc[i][0] * scale, acc[i][1] * scale,
                                    acc[i][2] * scale, acc[i][3] * scale);
            float4 o1 = make_float4(acc[i][4] * scale, acc[i][5] * scale,
                                    acc[i][6] * scale, acc[i][7] * scale);
            *(float4*)&g_h0[(size_t)row * FOUT + tx * 8]     = o0;
            *(float4*)&g_h0[(size_t)row * FOUT + tx * 8 + 4] = o1;
        }
    }
}

// ---------------- APPNP step: one WARP per dst node ----------------
// Lane l covers columns [l*4, l*4+4) and [128+l*4, 128+l*4+4) as float4s.
// Edges staged warp-cooperatively: lane i loads edge base+i, shfl-broadcast.
// insel: 0 = g_h0, 1 = g_za, 2 = dout;  outsel: 1 = g_za, 2 = dout
__global__ __launch_bounds__(256) void k_prop(int insel, int outsel,
                                              float* __restrict__ dout) {
    const float* zin;
    if (insel == 0)      zin = g_h0;
    else if (insel == 1) zin = g_za;
    else                 zin = dout;
    float* zout = (outsel == 1) ? g_za : dout;

    int warp = threadIdx.x >> 5;
    int lane = threadIdx.x & 31;
    int node = blockIdx.x * 8 + warp;
    if (node >= NNODES) return;

    int beg = g_rowptr[node];
    int end = g_rowptr[node + 1];

    float4 a0 = make_float4(0.f, 0.f, 0.f, 0.f);
    float4 a1 = make_float4(0.f, 0.f, 0.f, 0.f);

    for (int base = beg; base < end; base += 32) {
        int idx = base + lane;
        int   s = 0;
        float w = 0.f;
        if (idx < end) {
            int2 t = g_edge[idx];
            s = t.x;
            w = __int_as_float(t.y);
        }
        int cnt = min(32, end - base);
        for (int j = 0; j < cnt; j++) {
            int   sj = __shfl_sync(0xffffffffu, s, j);
            float wj = __shfl_sync(0xffffffffu, w, j);
            const float4* zp = (const float4*)&zin[(size_t)sj * FOUT];
            float4 z0 = zp[lane];
            float4 z1 = zp[lane + 32];
            a0.x += wj * z0.x; a0.y += wj * z0.y;
            a0.z += wj * z0.z; a0.w += wj * z0.w;
            a1.x += wj * z1.x; a1.y += wj * z1.y;
            a1.z += wj * z1.z; a1.w += wj * z1.w;
        }
    }

    const float4* hp = (const float4*)&g_h0[(size_t)node * FOUT];
    float4 h0v = hp[lane];
    float4 h1v = hp[lane + 32];
    float4 o0, o1;
    o0.x = 0.85f * a0.x + 0.15f * h0v.x;
    o0.y = 0.85f * a0.y + 0.15f * h0v.y;
    o0.z = 0.85f * a0.z + 0.15f * h0v.z;
    o0.w = 0.85f * a0.w + 0.15f * h0v.w;
    o1.x = 0.85f * a1.x + 0.15f * h1v.x;
    o1.y = 0.85f * a1.y + 0.15f * h1v.y;
    o1.z = 0.85f * a1.z + 0.15f * h1v.z;
    o1.w = 0.85f * a1.w + 0.15f * h1v.w;
    float4* op = (float4*)&zout[(size_t)node * FOUT];
    op[lane]      = o0;
    op[lane + 32] = o1;
}

// ---------------- launch ----------------
extern "C" void kernel_launch(void* const* d_in, const int* in_sizes, int n_in,
                              void* d_out, int out_size) {
    const float* x  = 0;
    const void*  ei = 0;
    const float* W1 = 0;
    const float* b1 = 0;
    for (int i = 0; i < n_in; i++) {
        int sz = in_sizes[i];
        if      (sz == NNODES * FIN) x  = (const float*)d_in[i];
        else if (sz == 2 * NEDGES)   ei = d_in[i];
        else if (sz == FOUT * FIN)   W1 = (const float*)d_in[i];
        else if (sz == FOUT)         b1 = (const float*)d_in[i];
    }
    float* out = (float*)d_out;
    int N = NNODES;
    int E = NEDGES;

    k_detect<<<1, 256>>>((const int*)ei, E);
    k_zero<<<(N + 255) / 256, 256>>>(N);
    k_count<<<(E + 255) / 256, 256>>>(ei, E, N);
    k_dinv<<<(N + 255) / 256, 256>>>(N);
    int nb = (N + 255) / 256;
    k_scanA<<<nb, 256>>>(N);
    k_scanB<<<1, 512>>>(nb);
    k_scanC<<<(N + 255) / 256, 256>>>(N, E + N);
    k_scatter<<<(E + N + 255) / 256, 256>>>(ei, E, N);

    k_gemm<<<(N + 63) / 64, 256>>>(x, W1, b1, N);

    // APPNP: k even writes g_za, k odd writes d_out; k=9 lands in d_out.
    int nprop = (N + 7) / 8;
    for (int k = 0; k < 10; k++) {
        int insel  = (k == 0) ? 0 : ((k & 1) ? 1 : 2);
        int outsel = (k & 1) ? 2 : 1;
        k_prop<<<nprop, 256>>>(insel, outsel, out);
    }
}

// round 6
// speedup vs baseline: 2.9046x; 1.5716x over previous
#include <cuda_runtime.h>
#include <cuda_fp16.h>

#define NNODES 100000
#define NEDGES 3200000
#define FIN 512
#define FOUT 256
#define TOTE (NEDGES + NNODES)

// ---------------- scratch (device globals; zero-init bss) ----------------
__device__ __align__(16) float  g_h0[(size_t)NNODES * FOUT];   // fp32 h0 (blend)
__device__ __align__(16) __half g_h0h[(size_t)NNODES * FOUT];  // fp16 h0 (z0)
__device__ __align__(16) __half g_zh0[(size_t)NNODES * FOUT];  // fp16 ping
__device__ __align__(16) __half g_zh1[(size_t)NNODES * FOUT];  // fp16 pong
__device__ int   g_cnt[NNODES];
__device__ float g_dinv[NNODES];
__device__ int   g_rowptr[NNODES + 1];
__device__ int   g_fill[NNODES];
__device__ int   g_bsum[512];
__device__ __align__(16) int2 g_edge[TOTE];   // (src, norm-as-int)
__device__ int   g_is64;

// ---------------- edge dtype detection ----------------
__global__ void k_detect(const int* __restrict__ e32, int E) {
    __shared__ int nz;
    if (threadIdx.x == 0) nz = 0;
    __syncthreads();
    int lim = min(E, 65536);
    for (int i = threadIdx.x; i < lim; i += blockDim.x)
        if (e32[2 * i + 1] != 0) nz = 1;   // benign race
    __syncthreads();
    if (threadIdx.x == 0) g_is64 = (nz == 0) ? 1 : 0;
}

__device__ __forceinline__ int edge_at(const void* ei, long long idx) {
    if (g_is64) return (int)((const long long*)ei)[idx];
    return ((const int*)ei)[idx];
}

// ---------------- graph preprocessing ----------------
__global__ void k_zero(int n) {
    int i = blockIdx.x * blockDim.x + threadIdx.x;
    if (i < n) { g_cnt[i] = 0; g_fill[i] = 0; }
}

__global__ void k_count(const void* __restrict__ ei, int E, int n) {
    int i = blockIdx.x * blockDim.x + threadIdx.x;
    if (i < E) {
        int d = edge_at(ei, (long long)E + i);
        d = min(max(d, 0), n - 1);
        atomicAdd(&g_cnt[d], 1);
    }
}

__global__ void k_dinv(int n) {
    int i = blockIdx.x * blockDim.x + threadIdx.x;
    if (i < n) {
        int c = g_cnt[i] + 1;               // + self loop
        g_cnt[i] = c;
        g_dinv[i] = rsqrtf((float)c);
    }
}

__global__ void k_scanA(int n) {
    __shared__ int sh[256];
    int tid = threadIdx.x;
    int i = blockIdx.x * 256 + tid;
    int v = (i < n) ? g_cnt[i] : 0;
    sh[tid] = v;
    __syncthreads();
    for (int off = 1; off < 256; off <<= 1) {
        int t = (tid >= off) ? sh[tid - off] : 0;
        __syncthreads();
        sh[tid] += t;
        __syncthreads();
    }
    if (i < n) g_rowptr[i] = sh[tid] - v;
    if (tid == 255) g_bsum[blockIdx.x] = sh[255];
}

__global__ void k_scanB(int nb) {
    __shared__ int sh[512];
    int tid = threadIdx.x;
    int v = (tid < nb) ? g_bsum[tid] : 0;
    sh[tid] = v;
    __syncthreads();
    for (int off = 1; off < 512; off <<= 1) {
        int t = (tid >= off) ? sh[tid - off] : 0;
        __syncthreads();
        sh[tid] += t;
        __syncthreads();
    }
    g_bsum[tid] = sh[tid] - v;
}

__global__ void k_scanC(int n, int total) {
    int i = blockIdx.x * blockDim.x + threadIdx.x;
    if (i < n) g_rowptr[i] += g_bsum[i >> 8];
    if (i == 0) g_rowptr[n] = total;
}

__global__ void k_scatter(const void* __restrict__ ei, int E, int n) {
    int i = blockIdx.x * blockDim.x + threadIdx.x;
    int tot = E + n;
    if (i >= tot) return;
    int s, d;
    if (i < E) {
        s = edge_at(ei, i);
        d = edge_at(ei, (long long)E + i);
        s = min(max(s, 0), n - 1);
        d = min(max(d, 0), n - 1);
    } else {
        s = d = i - E;
    }
    int pos = g_rowptr[d] + atomicAdd(&g_fill[d], 1);
    pos = min(max(pos, 0), tot - 1);
    float w = g_dinv[s] * g_dinv[d];
    g_edge[pos] = make_int2(s, __float_as_int(w));
}

// ---------------- fused GEMM + bias + L2-normalize*1.8 -> g_h0, g_h0h ----------------
__global__ __launch_bounds__(256) void k_gemm(const float* __restrict__ x,
                                              const float* __restrict__ W,
                                              const float* __restrict__ b,
                                              int N) {
    __shared__ __align__(16) float As[16][64];
    __shared__ __align__(16) float Ws[16][256];
    int tid = threadIdx.x;
    int tx = tid & 31, ty = tid >> 5;
    int n0 = blockIdx.x * 64;

    float acc[8][8];
#pragma unroll
    for (int i = 0; i < 8; i++)
#pragma unroll
        for (int j = 0; j < 8; j++) acc[i][j] = 0.0f;

    for (int k0 = 0; k0 < FIN; k0 += 16) {
        {
            int r = tid >> 2, kq = (tid & 3) * 4;
            float4 v = make_float4(0.f, 0.f, 0.f, 0.f);
            int row = n0 + r;
            if (row < N) v = *(const float4*)&x[(size_t)row * FIN + k0 + kq];
            As[kq + 0][r] = v.x; As[kq + 1][r] = v.y;
            As[kq + 2][r] = v.z; As[kq + 3][r] = v.w;
        }
        {
            int o = tid;
            const float* wp = &W[(size_t)o * FIN + k0];
            float4 w0 = *(const float4*)(wp);
            float4 w1 = *(const float4*)(wp + 4);
            float4 w2 = *(const float4*)(wp + 8);
            float4 w3 = *(const float4*)(wp + 12);
            Ws[0][o] = w0.x;  Ws[1][o] = w0.y;  Ws[2][o] = w0.z;  Ws[3][o] = w0.w;
            Ws[4][o] = w1.x;  Ws[5][o] = w1.y;  Ws[6][o] = w1.z;  Ws[7][o] = w1.w;
            Ws[8][o] = w2.x;  Ws[9][o] = w2.y;  Ws[10][o] = w2.z; Ws[11][o] = w2.w;
            Ws[12][o] = w3.x; Ws[13][o] = w3.y; Ws[14][o] = w3.z; Ws[15][o] = w3.w;
        }
        __syncthreads();
#pragma unroll
        for (int kk = 0; kk < 16; kk++) {
            float4 a0 = *(const float4*)&As[kk][ty * 8];
            float4 a1 = *(const float4*)&As[kk][ty * 8 + 4];
            float4 b0 = *(const float4*)&Ws[kk][tx * 8];
            float4 b1 = *(const float4*)&Ws[kk][tx * 8 + 4];
            float a[8]  = {a0.x, a0.y, a0.z, a0.w, a1.x, a1.y, a1.z, a1.w};
            float bb[8] = {b0.x, b0.y, b0.z, b0.w, b1.x, b1.y, b1.z, b1.w};
#pragma unroll
            for (int i = 0; i < 8; i++)
#pragma unroll
                for (int j = 0; j < 8; j++) acc[i][j] += a[i] * bb[j];
        }
        __syncthreads();
    }

    float bb[8];
#pragma unroll
    for (int j = 0; j < 8; j++) bb[j] = b[tx * 8 + j];
#pragma unroll
    for (int i = 0; i < 8; i++) {
        float ssq = 0.0f;
#pragma unroll
        for (int j = 0; j < 8; j++) {
            acc[i][j] += bb[j];
            ssq += acc[i][j] * acc[i][j];
        }
#pragma unroll
        for (int off = 16; off; off >>= 1)
            ssq += __shfl_xor_sync(0xffffffffu, ssq, off);
        float scale = 1.8f / fmaxf(sqrtf(ssq), 1e-12f);
        int row = n0 + ty * 8 + i;
        if (row < N) {
            float r0 = acc[i][0] * scale, r1 = acc[i][1] * scale;
            float r2 = acc[i][2] * scale, r3 = acc[i][3] * scale;
            float r4 = acc[i][4] * scale, r5 = acc[i][5] * scale;
            float r6 = acc[i][6] * scale, r7 = acc[i][7] * scale;
            *(float4*)&g_h0[(size_t)row * FOUT + tx * 8]     = make_float4(r0, r1, r2, r3);
            *(float4*)&g_h0[(size_t)row * FOUT + tx * 8 + 4] = make_float4(r4, r5, r6, r7);
            __half2 h01 = __floats2half2_rn(r0, r1);
            __half2 h23 = __floats2half2_rn(r2, r3);
            __half2 h45 = __floats2half2_rn(r4, r5);
            __half2 h67 = __floats2half2_rn(r6, r7);
            uint4 hv;
            hv.x = *(unsigned*)&h01; hv.y = *(unsigned*)&h23;
            hv.z = *(unsigned*)&h45; hv.w = *(unsigned*)&h67;
            *((uint4*)(g_h0h + (size_t)row * FOUT) + tx) = hv;
        }
    }
}

// ---------------- APPNP step: one WARP per dst node, fp16 z ----------------
// Lane l covers cols [8l, 8l+8): one uint4 (8 halves) per edge gather.
// insel: 0 = g_h0h, 1 = g_zh0, 2 = g_zh1
__device__ __forceinline__ void prop_gather(const __half* __restrict__ zin,
                                            int node, int lane,
                                            float acc[8]) {
    int beg = g_rowptr[node];
    int end = g_rowptr[node + 1];
    for (int base = beg; base < end; base += 32) {
        int idx = base + lane;
        int   s = 0;
        float w = 0.f;
        if (idx < end) {
            int2 t = g_edge[idx];
            s = t.x;
            w = __int_as_float(t.y);
        }
        int cnt = min(32, end - base);
        for (int j = 0; j < cnt; j++) {
            int   sj = __shfl_sync(0xffffffffu, s, j);
            float wj = __shfl_sync(0xffffffffu, w, j);
            uint4 v = *((const uint4*)(zin + (size_t)sj * FOUT) + lane);
            float2 f0 = __half22float2(*(__half2*)&v.x);
            float2 f1 = __half22float2(*(__half2*)&v.y);
            float2 f2 = __half22float2(*(__half2*)&v.z);
            float2 f3 = __half22float2(*(__half2*)&v.w);
            acc[0] += wj * f0.x; acc[1] += wj * f0.y;
            acc[2] += wj * f1.x; acc[3] += wj * f1.y;
            acc[4] += wj * f2.x; acc[5] += wj * f2.y;
            acc[6] += wj * f3.x; acc[7] += wj * f3.y;
        }
    }
}

__device__ __forceinline__ const __half* pick_h(int sel) {
    return sel == 0 ? g_h0h : (sel == 1 ? g_zh0 : g_zh1);
}

__global__ __launch_bounds__(256) void k_proph(int insel, int outsel) {
    const __half* zin = pick_h(insel);
    __half* zout = (outsel == 1) ? g_zh0 : g_zh1;
    int warp = threadIdx.x >> 5;
    int lane = threadIdx.x & 31;
    int node = blockIdx.x * 8 + warp;
    if (node >= NNODES) return;

    float a[8];
#pragma unroll
    for (int i = 0; i < 8; i++) a[i] = 0.f;
    prop_gather(zin, node, lane, a);

    const float4* hp = (const float4*)(g_h0 + (size_t)node * FOUT);
    float4 hA = hp[lane * 2];
    float4 hB = hp[lane * 2 + 1];
    float r0 = 0.85f * a[0] + 0.15f * hA.x;
    float r1 = 0.85f * a[1] + 0.15f * hA.y;
    float r2 = 0.85f * a[2] + 0.15f * hA.z;
    float r3 = 0.85f * a[3] + 0.15f * hA.w;
    float r4 = 0.85f * a[4] + 0.15f * hB.x;
    float r5 = 0.85f * a[5] + 0.15f * hB.y;
    float r6 = 0.85f * a[6] + 0.15f * hB.z;
    float r7 = 0.85f * a[7] + 0.15f * hB.w;
    __half2 h01 = __floats2half2_rn(r0, r1);
    __half2 h23 = __floats2half2_rn(r2, r3);
    __half2 h45 = __floats2half2_rn(r4, r5);
    __half2 h67 = __floats2half2_rn(r6, r7);
    uint4 hv;
    hv.x = *(unsigned*)&h01; hv.y = *(unsigned*)&h23;
    hv.z = *(unsigned*)&h45; hv.w = *(unsigned*)&h67;
    *((uint4*)(zout + (size_t)node * FOUT) + lane) = hv;
}

__global__ __launch_bounds__(256) void k_propf(int insel, float* __restrict__ dout) {
    const __half* zin = pick_h(insel);
    int warp = threadIdx.x >> 5;
    int lane = threadIdx.x & 31;
    int node = blockIdx.x * 8 + warp;
    if (node >= NNODES) return;

    float a[8];
#pragma unroll
    for (int i = 0; i < 8; i++) a[i] = 0.f;
    prop_gather(zin, node, lane, a);

    const float4* hp = (const float4*)(g_h0 + (size_t)node * FOUT);
    float4 hA = hp[lane * 2];
    float4 hB = hp[lane * 2 + 1];
    float4 oA, oB;
    oA.x = 0.85f * a[0] + 0.15f * hA.x;
    oA.y = 0.85f * a[1] + 0.15f * hA.y;
    oA.z = 0.85f * a[2] + 0.15f * hA.z;
    oA.w = 0.85f * a[3] + 0.15f * hA.w;
    oB.x = 0.85f * a[4] + 0.15f * hB.x;
    oB.y = 0.85f * a[5] + 0.15f * hB.y;
    oB.z = 0.85f * a[6] + 0.15f * hB.z;
    oB.w = 0.85f * a[7] + 0.15f * hB.w;
    float4* op = (float4*)(dout + (size_t)node * FOUT);
    op[lane * 2]     = oA;
    op[lane * 2 + 1] = oB;
}

// ---------------- launch ----------------
extern "C" void kernel_launch(void* const* d_in, const int* in_sizes, int n_in,
                              void* d_out, int out_size) {
    const float* x  = 0;
    const void*  ei = 0;
    const float* W1 = 0;
    const float* b1 = 0;
    for (int i = 0; i < n_in; i++) {
        int sz = in_sizes[i];
        if      (sz == NNODES * FIN) x  = (const float*)d_in[i];
        else if (sz == 2 * NEDGES)   ei = d_in[i];
        else if (sz == FOUT * FIN)   W1 = (const float*)d_in[i];
        else if (sz == FOUT)         b1 = (const float*)d_in[i];
    }
    float* out = (float*)d_out;
    int N = NNODES;
    int E = NEDGES;

    k_detect<<<1, 256>>>((const int*)ei, E);
    k_zero<<<(N + 255) / 256, 256>>>(N);
    k_count<<<(E + 255) / 256, 256>>>(ei, E, N);
    k_dinv<<<(N + 255) / 256, 256>>>(N);
    int nb = (N + 255) / 256;
    k_scanA<<<nb, 256>>>(N);
    k_scanB<<<1, 512>>>(nb);
    k_scanC<<<(N + 255) / 256, 256>>>(N, E + N);
    k_scatter<<<(E + N + 255) / 256, 256>>>(ei, E, N);

    k_gemm<<<(N + 63) / 64, 256>>>(x, W1, b1, N);

    // APPNP in fp16: step k writes buf (k even -> g_zh0, k odd -> g_zh1);
    // k=0 reads g_h0h; k=9 reads g_zh0 and writes fp32 d_out.
    int nprop = (N + 7) / 8;
    for (int k = 0; k < 9; k++) {
        int insel  = (k == 0) ? 0 : (((k - 1) & 1) ? 2 : 1);
        int outsel = (k & 1) ? 2 : 1;
        k_proph<<<nprop, 256>>>(insel, outsel);
    }
    k_propf<<<nprop, 256>>>(1, out);   // k=8 wrote g_zh0
}

// round 7
// speedup vs baseline: 3.7180x; 1.2800x over previous
#include <cuda_runtime.h>
#include <cuda_fp16.h>
#include <mma.h>

using namespace nvcuda;

#define NNODES 100000
#define NEDGES 3200000
#define FIN 512
#define FOUT 256
#define TOTE (NEDGES + NNODES)

// ---------------- scratch (device globals; zero-init bss) ----------------
__device__ __align__(16) __half g_h0h[(size_t)NNODES * FOUT];  // fp16 h0 (z0 + blend)
__device__ __align__(16) __half g_zh0[(size_t)NNODES * FOUT];  // fp16 ping
__device__ __align__(16) __half g_zh1[(size_t)NNODES * FOUT];  // fp16 pong
__device__ int   g_cnt[NNODES];
__device__ float g_dinv[NNODES];
__device__ int   g_rowptr[NNODES + 1];
__device__ int   g_fill[NNODES];
__device__ int   g_bsum[512];
__device__ __align__(16) int2 g_edge[TOTE];   // (src, norm-as-int)
__device__ int   g_is64;

// ---------------- edge dtype detection ----------------
__global__ void k_detect(const int* __restrict__ e32, int E) {
    __shared__ int nz;
    if (threadIdx.x == 0) nz = 0;
    __syncthreads();
    int lim = min(E, 65536);
    for (int i = threadIdx.x; i < lim; i += blockDim.x)
        if (e32[2 * i + 1] != 0) nz = 1;   // benign race
    __syncthreads();
    if (threadIdx.x == 0) g_is64 = (nz == 0) ? 1 : 0;
}

__device__ __forceinline__ int edge_at(const void* ei, long long idx) {
    if (g_is64) return (int)((const long long*)ei)[idx];
    return ((const int*)ei)[idx];
}

// ---------------- graph preprocessing ----------------
__global__ void k_zero(int n) {
    int i = blockIdx.x * blockDim.x + threadIdx.x;
    if (i < n) { g_cnt[i] = 0; g_fill[i] = 0; }
}

__global__ void k_count(const void* __restrict__ ei, int E, int n) {
    int i = blockIdx.x * blockDim.x + threadIdx.x;
    if (i < E) {
        int d = edge_at(ei, (long long)E + i);
        d = min(max(d, 0), n - 1);
        atomicAdd(&g_cnt[d], 1);
    }
}

__global__ void k_dinv(int n) {
    int i = blockIdx.x * blockDim.x + threadIdx.x;
    if (i < n) {
        int c = g_cnt[i] + 1;               // + self loop
        g_cnt[i] = c;
        g_dinv[i] = rsqrtf((float)c);
    }
}

__global__ void k_scanA(int n) {
    __shared__ int sh[256];
    int tid = threadIdx.x;
    int i = blockIdx.x * 256 + tid;
    int v = (i < n) ? g_cnt[i] : 0;
    sh[tid] = v;
    __syncthreads();
    for (int off = 1; off < 256; off <<= 1) {
        int t = (tid >= off) ? sh[tid - off] : 0;
        __syncthreads();
        sh[tid] += t;
        __syncthreads();
    }
    if (i < n) g_rowptr[i] = sh[tid] - v;
    if (tid == 255) g_bsum[blockIdx.x] = sh[255];
}

__global__ void k_scanB(int nb) {
    __shared__ int sh[512];
    int tid = threadIdx.x;
    int v = (tid < nb) ? g_bsum[tid] : 0;
    sh[tid] = v;
    __syncthreads();
    for (int off = 1; off < 512; off <<= 1) {
        int t = (tid >= off) ? sh[tid - off] : 0;
        __syncthreads();
        sh[tid] += t;
        __syncthreads();
    }
    g_bsum[tid] = sh[tid] - v;
}

__global__ void k_scanC(int n, int total) {
    int i = blockIdx.x * blockDim.x + threadIdx.x;
    if (i < n) g_rowptr[i] += g_bsum[i >> 8];
    if (i == 0) g_rowptr[n] = total;
}

__global__ void k_scatter(const void* __restrict__ ei, int E, int n) {
    int i = blockIdx.x * blockDim.x + threadIdx.x;
    int tot = E + n;
    if (i >= tot) return;
    int s, d;
    if (i < E) {
        s = edge_at(ei, i);
        d = edge_at(ei, (long long)E + i);
        s = min(max(s, 0), n - 1);
        d = min(max(d, 0), n - 1);
    } else {
        s = d = i - E;
    }
    int pos = g_rowptr[d] + atomicAdd(&g_fill[d], 1);
    pos = min(max(pos, 0), tot - 1);
    float w = g_dinv[s] * g_dinv[d];
    g_edge[pos] = make_int2(s, __float_as_int(w));
}

// -------- tensor-core GEMM + bias + L2-normalize*1.8 -> g_h0h (fp16) --------
// Block: 128 rows x 256 cols, 8 warps, each warp owns 16 full rows.
// BK=16; fp16 inputs (converted on stage-in), fp32 accumulate.
__global__ __launch_bounds__(256) void k_gemm_tc(const float* __restrict__ x,
                                                 const float* __restrict__ W,
                                                 const float* __restrict__ b,
                                                 int N) {
    __shared__ __align__(16) __half Ah[128][16];
    __shared__ __align__(16) __half Bh[256][16];
    __shared__ __align__(16) float  scr[8][256];   // per-warp 16x16 scratch
    __shared__ float bsh[256];

    int tid  = threadIdx.x;
    int w    = tid >> 5;
    int lane = tid & 31;
    int rows0 = blockIdx.x * 128;

    bsh[tid] = b[tid];

    wmma::fragment<wmma::accumulator, 16, 16, 16, float> acc[16];
#pragma unroll
    for (int n = 0; n < 16; n++) wmma::fill_fragment(acc[n], 0.0f);

    for (int k0 = 0; k0 < FIN; k0 += 16) {
        // stage x tile (128x16) -> fp16
        {
            int r = tid >> 1;
            int part = tid & 1;          // 0 or 1, 8 cols each
            int grow = rows0 + r;
            float4 v0 = make_float4(0.f, 0.f, 0.f, 0.f);
            float4 v1 = v0;
            if (grow < N) {
                const float* xp = &x[(size_t)grow * FIN + k0 + part * 8];
                v0 = *(const float4*)xp;
                v1 = *(const float4*)(xp + 4);
            }
            __half2 h0 = __floats2half2_rn(v0.x, v0.y);
            __half2 h1 = __floats2half2_rn(v0.z, v0.w);
            __half2 h2 = __floats2half2_rn(v1.x, v1.y);
            __half2 h3 = __floats2half2_rn(v1.z, v1.w);
            uint4 hv;
            hv.x = *(unsigned*)&h0; hv.y = *(unsigned*)&h1;
            hv.z = *(unsigned*)&h2; hv.w = *(unsigned*)&h3;
            *(uint4*)&Ah[r][part * 8] = hv;
        }
        // stage W tile (256x16) -> fp16
        {
            const float* wp = &W[(size_t)tid * FIN + k0];
            float4 w0 = *(const float4*)(wp);
            float4 w1 = *(const float4*)(wp + 4);
            float4 w2 = *(const float4*)(wp + 8);
            float4 w3 = *(const float4*)(wp + 12);
            __half2 h0 = __floats2half2_rn(w0.x, w0.y);
            __half2 h1 = __floats2half2_rn(w0.z, w0.w);
            __half2 h2 = __floats2half2_rn(w1.x, w1.y);
            __half2 h3 = __floats2half2_rn(w1.z, w1.w);
            __half2 h4 = __floats2half2_rn(w2.x, w2.y);
            __half2 h5 = __floats2half2_rn(w2.z, w2.w);
            __half2 h6 = __floats2half2_rn(w3.x, w3.y);
            __half2 h7 = __floats2half2_rn(w3.z, w3.w);
            uint4 a, c;
            a.x = *(unsigned*)&h0; a.y = *(unsigned*)&h1;
            a.z = *(unsigned*)&h2; a.w = *(unsigned*)&h3;
            c.x = *(unsigned*)&h4; c.y = *(unsigned*)&h5;
            c.z = *(unsigned*)&h6; c.w = *(unsigned*)&h7;
            *(uint4*)&Bh[tid][0] = a;
            *(uint4*)&Bh[tid][8] = c;
        }
        __syncthreads();

        wmma::fragment<wmma::matrix_a, 16, 16, 16, __half, wmma::row_major> af;
        wmma::load_matrix_sync(af, &Ah[w * 16][0], 16);
#pragma unroll
        for (int n = 0; n < 16; n++) {
            wmma::fragment<wmma::matrix_b, 16, 16, 16, __half, wmma::col_major> bf;
            wmma::load_matrix_sync(bf, &Bh[n * 16][0], 16);
            wmma::mma_sync(acc[n], af, bf, acc[n]);
        }
        __syncthreads();
    }

    // epilogue: bias + row L2 norm + scale, write fp16
    float* sc = scr[w];
    int lrow  = lane >> 1;          // 0..15 (warp-local row)
    int lcol0 = (lane & 1) * 8;     // 0 or 8 within 16-col frag
    float ssq = 0.0f;
#pragma unroll
    for (int n = 0; n < 16; n++) {
        wmma::store_matrix_sync(sc, acc[n], 16, wmma::mem_row_major);
        __syncwarp();
#pragma unroll
        for (int j = 0; j < 8; j++) {
            float v = sc[lrow * 16 + lcol0 + j] + bsh[n * 16 + lcol0 + j];
            ssq += v * v;
        }
        __syncwarp();
    }
    ssq += __shfl_xor_sync(0xffffffffu, ssq, 1);   // pair lanes complete the row
    float scale = 1.8f / fmaxf(sqrtf(ssq), 1e-12f);
    int grow = rows0 + w * 16 + lrow;
#pragma unroll
    for (int n = 0; n < 16; n++) {
        wmma::store_matrix_sync(sc, acc[n], 16, wmma::mem_row_major);
        __syncwarp();
        __half hv[8];
#pragma unroll
        for (int j = 0; j < 8; j++) {
            float v = (sc[lrow * 16 + lcol0 + j] + bsh[n * 16 + lcol0 + j]) * scale;
            hv[j] = __float2half_rn(v);
        }
        if (grow < N)
            *(uint4*)&g_h0h[(size_t)grow * FOUT + n * 16 + lcol0] = *(uint4*)hv;
        __syncwarp();
    }
}

// ---------------- APPNP step: one WARP per dst node, fp16 z ----------------
__device__ __forceinline__ void prop_gather(const __half* __restrict__ zin,
                                            int node, int lane,
                                            float acc[8]) {
    int beg = g_rowptr[node];
    int end = g_rowptr[node + 1];
    for (int base = beg; base < end; base += 32) {
        int idx = base + lane;
        int   s = 0;
        float w = 0.f;
        if (idx < end) {
            int2 t = g_edge[idx];
            s = t.x;
            w = __int_as_float(t.y);
        }
        int cnt = min(32, end - base);
        for (int j = 0; j < cnt; j++) {
            int   sj = __shfl_sync(0xffffffffu, s, j);
            float wj = __shfl_sync(0xffffffffu, w, j);
            uint4 v = *((const uint4*)(zin + (size_t)sj * FOUT) + lane);
            float2 f0 = __half22float2(*(__half2*)&v.x);
            float2 f1 = __half22float2(*(__half2*)&v.y);
            float2 f2 = __half22float2(*(__half2*)&v.z);
            float2 f3 = __half22float2(*(__half2*)&v.w);
            acc[0] += wj * f0.x; acc[1] += wj * f0.y;
            acc[2] += wj * f1.x; acc[3] += wj * f1.y;
            acc[4] += wj * f2.x; acc[5] += wj * f2.y;
            acc[6] += wj * f3.x; acc[7] += wj * f3.y;
        }
    }
}

__device__ __forceinline__ const __half* pick_h(int sel) {
    return sel == 0 ? g_h0h : (sel == 1 ? g_zh0 : g_zh1);
}

__device__ __forceinline__ void blend_h0(int node, int lane, float a[8],
                                         float r[8]) {
    uint4 hv = *((const uint4*)(g_h0h + (size_t)node * FOUT) + lane);
    float2 f0 = __half22float2(*(__half2*)&hv.x);
    float2 f1 = __half22float2(*(__half2*)&hv.y);
    float2 f2 = __half22float2(*(__half2*)&hv.z);
    float2 f3 = __half22float2(*(__half2*)&hv.w);
    r[0] = 0.85f * a[0] + 0.15f * f0.x;
    r[1] = 0.85f * a[1] + 0.15f * f0.y;
    r[2] = 0.85f * a[2] + 0.15f * f1.x;
    r[3] = 0.85f * a[3] + 0.15f * f1.y;
    r[4] = 0.85f * a[4] + 0.15f * f2.x;
    r[5] = 0.85f * a[5] + 0.15f * f2.y;
    r[6] = 0.85f * a[6] + 0.15f * f3.x;
    r[7] = 0.85f * a[7] + 0.15f * f3.y;
}

__global__ __launch_bounds__(256) void k_proph(int insel, int outsel) {
    const __half* zin = pick_h(insel);
    __half* zout = (outsel == 1) ? g_zh0 : g_zh1;
    int warp = threadIdx.x >> 5;
    int lane = threadIdx.x & 31;
    int node = blockIdx.x * 8 + warp;
    if (node >= NNODES) return;

    float a[8];
#pragma unroll
    for (int i = 0; i < 8; i++) a[i] = 0.f;
    prop_gather(zin, node, lane, a);

    float r[8];
    blend_h0(node, lane, a, r);
    __half2 h01 = __floats2half2_rn(r[0], r[1]);
    __half2 h23 = __floats2half2_rn(r[2], r[3]);
    __half2 h45 = __floats2half2_rn(r[4], r[5]);
    __half2 h67 = __floats2half2_rn(r[6], r[7]);
    uint4 hv;
    hv.x = *(unsigned*)&h01; hv.y = *(unsigned*)&h23;
    hv.z = *(unsigned*)&h45; hv.w = *(unsigned*)&h67;
    *((uint4*)(zout + (size_t)node * FOUT) + lane) = hv;
}

__global__ __launch_bounds__(256) void k_propf(int insel, float* __restrict__ dout) {
    const __half* zin = pick_h(insel);
    int warp = threadIdx.x >> 5;
    int lane = threadIdx.x & 31;
    int node = blockIdx.x * 8 + warp;
    if (node >= NNODES) return;

    float a[8];
#pragma unroll
    for (int i = 0; i < 8; i++) a[i] = 0.f;
    prop_gather(zin, node, lane, a);

    float r[8];
    blend_h0(node, lane, a, r);
    float4* op = (float4*)(dout + (size_t)node * FOUT);
    op[lane * 2]     = make_float4(r[0], r[1], r[2], r[3]);
    op[lane * 2 + 1] = make_float4(r[4], r[5], r[6], r[7]);
}

// ---------------- launch ----------------
extern "C" void kernel_launch(void* const* d_in, const int* in_sizes, int n_in,
                              void* d_out, int out_size) {
    const float* x  = 0;
    const void*  ei = 0;
    const float* W1 = 0;
    const float* b1 = 0;
    for (int i = 0; i < n_in; i++) {
        int sz = in_sizes[i];
        if      (sz == NNODES * FIN) x  = (const float*)d_in[i];
        else if (sz == 2 * NEDGES)   ei = d_in[i];
        else if (sz == FOUT * FIN)   W1 = (const float*)d_in[i];
        else if (sz == FOUT)         b1 = (const float*)d_in[i];
    }
    float* out = (float*)d_out;
    int N = NNODES;
    int E = NEDGES;

    k_detect<<<1, 256>>>((const int*)ei, E);
    k_zero<<<(N + 255) / 256, 256>>>(N);
    k_count<<<(E + 255) / 256, 256>>>(ei, E, N);
    k_dinv<<<(N + 255) / 256, 256>>>(N);
    int nb = (N + 255) / 256;
    k_scanA<<<nb, 256>>>(N);
    k_scanB<<<1, 512>>>(nb);
    k_scanC<<<(N + 255) / 256, 256>>>(N, E + N);
    k_scatter<<<(E + N + 255) / 256, 256>>>(ei, E, N);

    k_gemm_tc<<<(N + 127) / 128, 256>>>(x, W1, b1, N);

    // APPNP in fp16: step k writes (k even -> g_zh0, k odd -> g_zh1);
    // k=0 reads g_h0h; k=9 reads g_zh0 and writes fp32 d_out.
    int nprop = (N + 7) / 8;
    for (int k = 0; k < 9; k++) {
        int insel  = (k == 0) ? 0 : (((k - 1) & 1) ? 2 : 1);
        int outsel = (k & 1) ? 2 : 1;
        k_proph<<<nprop, 256>>>(insel, outsel);
    }
    k_propf<<<nprop, 256>>>(1, out);   // k=8 wrote g_zh0
}